// round 6
// baseline (speedup 1.0000x reference)
#include <cuda_runtime.h>

#define H_N      1500
#define G4       6000
#define T_STEPS  4096
#define MLP_HID_N 1875
#define OUT_N    20
#define IN_N     20
#define NCTA     148
#define NTHREADS 512
#define NREP     8           // h replication factor (L2 de-hotspot)
#define MAXB     12          // max plane-B rows (smem)
#define WPAD_B   1506        // B row stride (floats): 753 = 1 mod 16 -> conflict-free LDS.64
#define MAXROWS  44
#define NCHUNK   24          // max float4 column-chunks per warp (375 = 7*24 + 9*23)

// ---------------- device scratch ----------------
__device__ float    g_xp[(size_t)T_STEPS * G4];
__device__ float    g_hrep[2][NREP][1504];     // double-buffered, 8-way replicated h
__device__ float    g_hid[MLP_HID_N];
__device__ unsigned g_flag[160];               // per-CTA step flags (monotonic)

#define FMA2(acc, a, b) \
    asm("fma.rn.f32x2 %0, %1, %2, %0;" : "+l"(acc) : "l"(a), "l"(b))

__device__ __forceinline__ float sigmoid_f(float x) {
    return __fdividef(1.f, 1.f + __expf(-x));
}
__device__ __forceinline__ float tanh_f(float x) {
    return __fdividef(2.f, 1.f + __expf(-2.f * x)) - 1.f;
}

__device__ __forceinline__ unsigned ld_acq(const unsigned* p) {
    unsigned v;
    asm volatile("ld.acquire.gpu.global.u32 %0, [%1];" : "=r"(v) : "l"(p) : "memory");
    return v;
}
__device__ __forceinline__ void st_rel(unsigned* p, unsigned v) {
    asm volatile("st.release.gpu.global.u32 [%0], %1;" :: "l"(p), "r"(v) : "memory");
}

// flag barrier: warp 0 of each CTA; own flag already stored by caller
__device__ __forceinline__ void flag_wait_all(int lane, unsigned tgt) {
    bool ok;
    do {
        unsigned v0 = ld_acq(&g_flag[lane]);
        unsigned v1 = ld_acq(&g_flag[lane + 32]);
        unsigned v2 = ld_acq(&g_flag[lane + 64]);
        unsigned v3 = ld_acq(&g_flag[lane + 96]);
        unsigned v4 = (lane < 20) ? ld_acq(&g_flag[lane + 128]) : tgt;
        unsigned m01 = v0 < v1 ? v0 : v1;
        unsigned m23 = v2 < v3 ? v2 : v3;
        unsigned m = m01 < m23 ? m01 : m23;
        m = m < v4 ? m : v4;
        ok = __all_sync(0xffffffffu, m >= tgt);
    } while (!ok);
}

// ---------------- pre: init state + x_proj ----------------
__global__ void pre_kernel(const float* __restrict__ inp,
                           const float* __restrict__ W_ih,
                           const float* __restrict__ b_ih,
                           const float* __restrict__ b_hh) {
    __shared__ float Wsm[256 * 21];
    __shared__ float bsm[256];
    __shared__ float insm[128 * IN_N];
    int tid = threadIdx.x;
    int r0 = blockIdx.x * 256;
    int t0 = blockIdx.y * 128;

    if (blockIdx.x == 0 && blockIdx.y == 0) {
        float* hz = &g_hrep[0][0][0];
        for (int i = tid; i < 2 * NREP * 1504; i += 256) hz[i] = 0.f;
        for (int i = tid; i < 160; i += 256) g_flag[i] = 0u;
    }

    for (int i = tid; i < 256 * IN_N; i += 256) {
        int rr = i / IN_N, k = i % IN_N;
        int row = r0 + rr;
        Wsm[rr * 21 + k] = (row < G4) ? W_ih[row * IN_N + k] : 0.f;
    }
    {
        int row = r0 + tid;
        bsm[tid] = (row < G4) ? (b_ih[row] + b_hh[row]) : 0.f;
    }
    for (int i = tid; i < 128 * IN_N; i += 256)
        insm[i] = inp[t0 * IN_N + i];
    __syncthreads();

    int row = r0 + tid;
    if (row < G4) {
        const float* wrow = &Wsm[tid * 21];
        float bias = bsm[tid];
        for (int tt = 0; tt < 128; tt++) {
            const float* ir = &insm[tt * IN_N];
            float acc = bias;
            #pragma unroll
            for (int k = 0; k < IN_N; k++) acc += ir[k] * wrow[k];
            g_xp[(size_t)(t0 + tt) * G4 + row] = acc;
        }
    }
}

// ---------------- persistent LSTM + MLP ----------------
__global__ void __launch_bounds__(NTHREADS, 1)
lstm_kernel(const float* __restrict__ W_hh,
            const float* __restrict__ W1,
            const float* __restrict__ b1,
            const float* __restrict__ W2,
            const float* __restrict__ b2,
            float* __restrict__ out) {
    extern __shared__ float smem[];
    float* Wb_s  = smem;                         // MAXB * WPAD_B
    float* h_s   = Wb_s + MAXB * WPAD_B;         // 1504
    float* part  = h_s + 1504;                   // MAXROWS * 17
    float* xp_s  = part + MAXROWS * 17;          // MAXROWS
    float* c_s   = xp_s + MAXROWS;               // 16

    const int tid  = threadIdx.x;
    const int lane = tid & 31;
    const int w    = tid >> 5;
    const int b    = blockIdx.x;
    const int nu   = (b < 20) ? 11 : 10;
    const int u0   = (b < 20) ? b * 11 : 220 + (b - 20) * 10;
    const int nrows = 4 * nu;
    const int nA    = 32;                        // plane-A rows (registers, lane=row)
    const int nB    = nrows - 32;                // plane-B rows (smem): 12 or 8

    const int NK    = (w < 7) ? 24 : 23;
    const int start = (w < 7) ? w * 24 : 168 + (w - 7) * 23;

    // ---- preload plane-B weights (rows 32..nrows) into smem, float2 granularity ----
    for (int idx = tid; idx < nB * 753; idx += NTHREADS) {
        int r = idx / 753, j = idx % 753;
        float2 v = make_float2(0.f, 0.f);
        if (j < 750) {
            int lr = 32 + r;
            int grow = (lr / nu) * H_N + u0 + (lr % nu);
            v = *(const float2*)&W_hh[(size_t)grow * H_N + j * 2];
        }
        *(float2*)&Wb_s[r * WPAD_B + j * 2] = v;
    }
    if (tid < nu) c_s[tid] = 0.f;

    // ---- preload plane-A weights (row = lane, all 32 lanes) into registers ----
    ulonglong2 wA[NCHUNK];
    {
        int grow = (lane / nu) * H_N + u0 + (lane % nu);
        const float* wrowA = &W_hh[(size_t)grow * H_N];
        #pragma unroll
        for (int k = 0; k < NCHUNK; k++) {
            if (k < NK)
                wA[k] = *(const ulonglong2*)&wrowA[(start + k) * 4];
            else
                wA[k] = make_ulonglong2(0ull, 0ull);
        }
    }

    // plane-B: lanes mirror rows (lane % nB); broadcasts are free
    const float* wrowB = &Wb_s[(lane % nB) * WPAD_B];

    int xrow = 0;
    if (tid < nrows) xrow = (tid / nu) * H_N + u0 + (tid % nu);

    // prefetch xp for t=0
    float xp_cur = 0.f;
    if (tid < nrows) xp_cur = __ldcs(&g_xp[xrow]);

    __syncthreads();

    for (int t = 0; t < T_STEPS; t++) {
        // prefetch xp for t+1
        float xp_next = 0.f;
        if (tid < nrows && t + 1 < T_STEPS)
            xp_next = __ldcs(&g_xp[(size_t)(t + 1) * G4 + xrow]);

        // fetch h(t) from this CTA's replica and stage to smem
        const float* hb = g_hrep[t & 1][b & (NREP - 1)];
        if (tid < 376) {
            float4 hv4 = __ldcg((const float4*)&hb[tid * 4]);
            *(float4*)&h_s[tid * 4] = hv4;
        }
        __syncthreads();

        // ---- matvec: packed f32x2 FMAs; plane-B via conflict-free LDS.64 ----
        unsigned long long aA0 = 0ull, aA1 = 0ull, aB0 = 0ull, aB1 = 0ull;
        const float* hbase = &h_s[start * 4];
        #pragma unroll
        for (int k = 0; k < NCHUNK; k++) {
            ulonglong2 hv = (k < NK) ? *(const ulonglong2*)&hbase[k * 4]
                                     : make_ulonglong2(0ull, 0ull);
            FMA2(aA0, wA[k].x, hv.x);
            FMA2(aA1, wA[k].y, hv.y);
            unsigned long long wb0 = 0ull, wb1 = 0ull;
            if (k < NK) {
                wb0 = *(const unsigned long long*)&wrowB[(start + k) * 4];
                wb1 = *(const unsigned long long*)&wrowB[(start + k) * 4 + 2];
            }
            FMA2(aB0, wb0, hv.x);
            FMA2(aB1, wb1, hv.y);
        }
        float accA, accB;
        {
            float2 a0 = *(float2*)&aA0, a1 = *(float2*)&aA1;
            accA = (a0.x + a0.y) + (a1.x + a1.y);
            float2 b0 = *(float2*)&aB0, b1 = *(float2*)&aB1;
            accB = (b0.x + b0.y) + (b1.x + b1.y);
        }
        part[lane * 17 + w] = accA;                       // all 32 A rows valid
        if (lane < nB) part[(32 + lane) * 17 + w] = accB;
        if (tid < nrows) xp_s[tid] = xp_cur;
        __syncthreads();

        // ---- per-unit reduce + gates: warp u owns hidden unit u ----
        if (w < nu) {
            float g4v[4];
            #pragma unroll
            for (int gg = 0; gg < 4; gg++) {
                int row = gg * nu + w;
                float v = (lane < 16) ? part[row * 17 + lane] : 0.f;
                v += __shfl_xor_sync(0xffffffffu, v, 8);
                v += __shfl_xor_sync(0xffffffffu, v, 4);
                v += __shfl_xor_sync(0xffffffffu, v, 2);
                v += __shfl_xor_sync(0xffffffffu, v, 1);
                g4v[gg] = v + xp_s[row];
            }
            int sel = lane & 3;
            float gv = g4v[sel];
            float act = (sel == 2) ? tanh_f(gv) : sigmoid_f(gv);
            float ig = __shfl_sync(0xffffffffu, act, 0);
            float fg = __shfl_sync(0xffffffffu, act, 1);
            float gg = __shfl_sync(0xffffffffu, act, 2);
            float og = __shfl_sync(0xffffffffu, act, 3);
            float hval = 0.f;
            if (lane == 0) {
                float c = fg * c_s[w] + ig * gg;
                c_s[w] = c;
                hval = og * tanh_f(c);
            }
            hval = __shfl_sync(0xffffffffu, hval, 0);
            if (lane < NREP)
                g_hrep[(t + 1) & 1][lane][u0 + w] = hval;
        }
        xp_cur = xp_next;
        __syncthreads();

        // ---- flag barrier: parallel release stores + coalesced acquire poll ----
        if (w == 0) {
            if (lane == 0) st_rel(&g_flag[b], (unsigned)(t + 1));
            flag_wait_all(lane, (unsigned)(t + 1));
        }
        __syncthreads();
    }

    // =================== MLP head (h final in g_hrep[0][*]) ===================
    {
        int gw = b * 16 + w;
        if (gw < MLP_HID_N) {
            const float* wr = &W1[(size_t)gw * H_N];
            const float* hv = g_hrep[0][b & (NREP - 1)];
            float acc = 0.f;
            for (int c4 = lane; c4 < 375; c4 += 32) {
                float4 wv = *(const float4*)&wr[c4 * 4];
                float4 h4 = __ldcg((const float4*)&hv[c4 * 4]);
                acc += wv.x * h4.x + wv.y * h4.y + wv.z * h4.z + wv.w * h4.w;
            }
            acc += __shfl_xor_sync(0xffffffffu, acc, 16);
            acc += __shfl_xor_sync(0xffffffffu, acc, 8);
            acc += __shfl_xor_sync(0xffffffffu, acc, 4);
            acc += __shfl_xor_sync(0xffffffffu, acc, 2);
            acc += __shfl_xor_sync(0xffffffffu, acc, 1);
            if (lane == 0) g_hid[gw] = acc + b1[gw];
        }
        __syncthreads();
        if (tid == 0) st_rel(&g_flag[b], (unsigned)(T_STEPS + 1));

        if (b == 0) {
            if (w == 0) flag_wait_all(lane, (unsigned)(T_STEPS + 1));
            __syncthreads();
            for (int r = w; r < OUT_N; r += 16) {
                const float* wr = &W2[(size_t)r * MLP_HID_N];
                float acc = 0.f;
                for (int c = lane; c < MLP_HID_N; c += 32)
                    acc += wr[c] * __ldcg(&g_hid[c]);
                acc += __shfl_xor_sync(0xffffffffu, acc, 16);
                acc += __shfl_xor_sync(0xffffffffu, acc, 8);
                acc += __shfl_xor_sync(0xffffffffu, acc, 4);
                acc += __shfl_xor_sync(0xffffffffu, acc, 2);
                acc += __shfl_xor_sync(0xffffffffu, acc, 1);
                if (lane == 0) out[r] = acc + b2[r];
            }
        }
    }
}

// ---------------- launch ----------------
extern "C" void kernel_launch(void* const* d_in, const int* in_sizes, int n_in,
                              void* d_out, int out_size) {
    const float* inp  = (const float*)d_in[0];
    const float* W_ih = (const float*)d_in[1];
    const float* W_hh = (const float*)d_in[2];
    const float* b_ih = (const float*)d_in[3];
    const float* b_hh = (const float*)d_in[4];
    const float* W1   = (const float*)d_in[5];
    const float* b1   = (const float*)d_in[6];
    const float* W2   = (const float*)d_in[7];
    const float* b2   = (const float*)d_in[8];
    float* out = (float*)d_out;

    size_t smem_bytes = (size_t)(MAXB * WPAD_B + 1504 + MAXROWS * 17 + MAXROWS + 16)
                        * sizeof(float);
    cudaFuncSetAttribute(lstm_kernel, cudaFuncAttributeMaxDynamicSharedMemorySize,
                         (int)smem_bytes);

    pre_kernel<<<dim3(24, 32), 256>>>(inp, W_ih, b_ih, b_hh);
    lstm_kernel<<<NCTA, NTHREADS, smem_bytes>>>(W_hh, W1, b1, W2, b2, out);
}

// round 7
// speedup vs baseline: 1.3497x; 1.3497x over previous
#include <cuda_runtime.h>

#define H_N      1500
#define G4       6000
#define T_STEPS  4096
#define MLP_HID_N 1875
#define OUT_N    20
#define IN_N     20
#define NCTA     125         // 125 CTAs x 12 units = 1500: perfectly balanced
#define NTHREADS 512
#define NU       12          // hidden units per CTA
#define NROWS    48          // gate rows per CTA
#define NB       16          // plane-B rows (smem)
#define NREP     4           // h replication factor
#define WPAD_B   1508        // B row stride (floats); LDS.128 conflict deg 2 (benign)
#define NCHUNK   24          // max float4 column-chunks per warp (375 = 7*24 + 9*23)

// ---------------- device scratch ----------------
__device__ float    g_xp[(size_t)T_STEPS * G4];
__device__ float    g_hrep[2][NREP][1504];     // double-buffered, replicated h
__device__ float    g_hid[MLP_HID_N];
__device__ unsigned g_count;                   // arrival counter (monotonic per launch)

#define FMA2(acc, a, b) \
    asm("fma.rn.f32x2 %0, %1, %2, %0;" : "+l"(acc) : "l"(a), "l"(b))

__device__ __forceinline__ float sigmoid_f(float x) {
    return __fdividef(1.f, 1.f + __expf(-x));
}
__device__ __forceinline__ float tanh_f(float x) {
    return __fdividef(2.f, 1.f + __expf(-2.f * x)) - 1.f;
}

// ---------------- grid barrier (R3-proven form) ----------------
__device__ __forceinline__ void gb_arrive_wait(unsigned target) {
    asm volatile("red.release.gpu.global.add.u32 [%0], 1;"
                 :: "l"(&g_count) : "memory");
    unsigned v;
    do {
        asm volatile("ld.acquire.gpu.global.u32 %0, [%1];"
                     : "=r"(v) : "l"(&g_count) : "memory");
    } while (v < target);
}

// ---------------- pre: init state + x_proj ----------------
__global__ void pre_kernel(const float* __restrict__ inp,
                           const float* __restrict__ W_ih,
                           const float* __restrict__ b_ih,
                           const float* __restrict__ b_hh) {
    __shared__ float Wsm[256 * 21];
    __shared__ float bsm[256];
    __shared__ float insm[128 * IN_N];
    int tid = threadIdx.x;
    int r0 = blockIdx.x * 256;
    int t0 = blockIdx.y * 128;

    if (blockIdx.x == 0 && blockIdx.y == 0) {
        float* hz = &g_hrep[0][0][0];
        for (int i = tid; i < 2 * NREP * 1504; i += 256) hz[i] = 0.f;
        if (tid == 0) g_count = 0u;
    }

    for (int i = tid; i < 256 * IN_N; i += 256) {
        int rr = i / IN_N, k = i % IN_N;
        int row = r0 + rr;
        Wsm[rr * 21 + k] = (row < G4) ? W_ih[row * IN_N + k] : 0.f;
    }
    {
        int row = r0 + tid;
        bsm[tid] = (row < G4) ? (b_ih[row] + b_hh[row]) : 0.f;
    }
    for (int i = tid; i < 128 * IN_N; i += 256)
        insm[i] = inp[t0 * IN_N + i];
    __syncthreads();

    int row = r0 + tid;
    if (row < G4) {
        const float* wrow = &Wsm[tid * 21];
        float bias = bsm[tid];
        for (int tt = 0; tt < 128; tt++) {
            const float* ir = &insm[tt * IN_N];
            float acc = bias;
            #pragma unroll
            for (int k = 0; k < IN_N; k++) acc += ir[k] * wrow[k];
            g_xp[(size_t)(t0 + tt) * G4 + row] = acc;
        }
    }
}

// ---------------- persistent LSTM + MLP ----------------
__global__ void __launch_bounds__(NTHREADS, 1)
lstm_kernel(const float* __restrict__ W_hh,
            const float* __restrict__ W1,
            const float* __restrict__ b1,
            const float* __restrict__ W2,
            const float* __restrict__ b2,
            float* __restrict__ out) {
    extern __shared__ float smem[];
    float* Wb_s  = smem;                         // NB * WPAD_B
    float* h_s   = Wb_s + NB * WPAD_B;           // 1504
    float* part  = h_s + 1504;                   // NROWS * 17
    float* xp_s  = part + NROWS * 17;            // NROWS
    float* c_s   = xp_s + NROWS;                 // 16

    const int tid  = threadIdx.x;
    const int lane = tid & 31;
    const int w    = tid >> 5;
    const int b    = blockIdx.x;
    const int u0   = b * NU;

    const int NK    = (w < 7) ? 24 : 23;
    const int start = (w < 7) ? w * 24 : 168 + (w - 7) * 23;

    // ---- preload plane-B weights (rows 32..47) into smem ----
    for (int idx = tid; idx < NB * 377; idx += NTHREADS) {
        int r = idx / 377, c4 = idx % 377;
        float4 v = make_float4(0.f, 0.f, 0.f, 0.f);
        if (c4 < 375) {
            int lr = 32 + r;
            int grow = (lr / NU) * H_N + u0 + (lr % NU);
            v = *(const float4*)&W_hh[(size_t)grow * H_N + c4 * 4];
        }
        *(float4*)&Wb_s[r * WPAD_B + c4 * 4] = v;
    }
    if (tid < NU) c_s[tid] = 0.f;

    // ---- preload plane-A weights (row = lane, 32 rows) into registers ----
    ulonglong2 wA[NCHUNK];
    {
        int grow = (lane / NU) * H_N + u0 + (lane % NU);
        const float* wrowA = &W_hh[(size_t)grow * H_N];
        #pragma unroll
        for (int k = 0; k < NCHUNK; k++) {
            if (k < NK)
                wA[k] = *(const ulonglong2*)&wrowA[(start + k) * 4];
            else
                wA[k] = make_ulonglong2(0ull, 0ull);
        }
    }

    // plane-B: lanes mirror rows (lane % 16)
    const float* wrowB = &Wb_s[(lane & (NB - 1)) * WPAD_B];

    int xrow = 0;
    if (tid < NROWS) xrow = (tid / NU) * H_N + u0 + (tid % NU);

    // prefetch xp for t=0
    float xp_cur = 0.f;
    if (tid < NROWS) xp_cur = __ldcs(&g_xp[xrow]);

    __syncthreads();

    for (int t = 0; t < T_STEPS; t++) {
        // h(t) load first (critical path), then xp(t+1) prefetch (off-path)
        const float* hb = g_hrep[t & 1][b & (NREP - 1)];
        float4 hv4;
        if (tid < 376) hv4 = __ldcg((const float4*)&hb[tid * 4]);
        float xp_next = 0.f;
        if (tid < NROWS && t + 1 < T_STEPS)
            xp_next = __ldcs(&g_xp[(size_t)(t + 1) * G4 + xrow]);
        if (tid < 376) *(float4*)&h_s[tid * 4] = hv4;
        __syncthreads();

        // ---- matvec: packed f32x2 FMAs; A from regs, B via LDS.128 ----
        unsigned long long aA0 = 0ull, aA1 = 0ull, aB0 = 0ull, aB1 = 0ull;
        const float* hbase = &h_s[start * 4];
        #pragma unroll
        for (int k = 0; k < NCHUNK; k++) {
            ulonglong2 hv = (k < NK) ? *(const ulonglong2*)&hbase[k * 4]
                                     : make_ulonglong2(0ull, 0ull);
            FMA2(aA0, wA[k].x, hv.x);
            FMA2(aA1, wA[k].y, hv.y);
            ulonglong2 wb = (k < NK) ? *(const ulonglong2*)&wrowB[(start + k) * 4]
                                     : make_ulonglong2(0ull, 0ull);
            FMA2(aB0, wb.x, hv.x);
            FMA2(aB1, wb.y, hv.y);
        }
        float accA, accB;
        {
            float2 a0 = *(float2*)&aA0, a1 = *(float2*)&aA1;
            accA = (a0.x + a0.y) + (a1.x + a1.y);
            float2 b0 = *(float2*)&aB0, b1 = *(float2*)&aB1;
            accB = (b0.x + b0.y) + (b1.x + b1.y);
        }
        part[lane * 17 + w] = accA;                       // 32 A rows
        if (lane < NB) part[(32 + lane) * 17 + w] = accB; // 16 B rows
        if (tid < NROWS) xp_s[tid] = xp_cur;
        __syncthreads();

        // ---- per-unit reduce + gates: warp u owns hidden unit u ----
        if (w < NU) {
            float g4v[4];
            #pragma unroll
            for (int gg = 0; gg < 4; gg++) {
                int row = gg * NU + w;
                float v = (lane < 16) ? part[row * 17 + lane] : 0.f;
                v += __shfl_xor_sync(0xffffffffu, v, 8);
                v += __shfl_xor_sync(0xffffffffu, v, 4);
                v += __shfl_xor_sync(0xffffffffu, v, 2);
                v += __shfl_xor_sync(0xffffffffu, v, 1);
                g4v[gg] = v + xp_s[row];
            }
            int sel = lane & 3;
            float gv = g4v[sel];
            float act = (sel == 2) ? tanh_f(gv) : sigmoid_f(gv);
            float ig = __shfl_sync(0xffffffffu, act, 0);
            float fg = __shfl_sync(0xffffffffu, act, 1);
            float gg = __shfl_sync(0xffffffffu, act, 2);
            float og = __shfl_sync(0xffffffffu, act, 3);
            float hval = 0.f;
            if (lane == 0) {
                float c = fg * c_s[w] + ig * gg;
                c_s[w] = c;
                hval = og * tanh_f(c);
            }
            hval = __shfl_sync(0xffffffffu, hval, 0);
            if (lane < NREP)
                g_hrep[(t + 1) & 1][lane][u0 + w] = hval;
        }
        xp_cur = xp_next;
        __syncthreads();

        // ---- grid barrier (R3 form) ----
        if (tid == 0) gb_arrive_wait((unsigned)NCTA * (unsigned)(t + 1));
        __syncthreads();
    }

    // =================== MLP head (h final in g_hrep[0][*]) ===================
    {
        int gw = b * 16 + w;
        if (gw < MLP_HID_N) {
            const float* wr = &W1[(size_t)gw * H_N];
            const float* hv = g_hrep[0][b & (NREP - 1)];
            float acc = 0.f;
            for (int c4 = lane; c4 < 375; c4 += 32) {
                float4 wv = *(const float4*)&wr[c4 * 4];
                float4 h4 = __ldcg((const float4*)&hv[c4 * 4]);
                acc += wv.x * h4.x + wv.y * h4.y + wv.z * h4.z + wv.w * h4.w;
            }
            acc += __shfl_xor_sync(0xffffffffu, acc, 16);
            acc += __shfl_xor_sync(0xffffffffu, acc, 8);
            acc += __shfl_xor_sync(0xffffffffu, acc, 4);
            acc += __shfl_xor_sync(0xffffffffu, acc, 2);
            acc += __shfl_xor_sync(0xffffffffu, acc, 1);
            if (lane == 0) g_hid[gw] = acc + b1[gw];
        }
        __syncthreads();
        if (tid == 0) {
            asm volatile("red.release.gpu.global.add.u32 [%0], 1;"
                         :: "l"(&g_count) : "memory");
        }

        if (b == 0) {
            if (tid == 0) {
                unsigned v, target = (unsigned)NCTA * (unsigned)(T_STEPS + 1);
                do {
                    asm volatile("ld.acquire.gpu.global.u32 %0, [%1];"
                                 : "=r"(v) : "l"(&g_count) : "memory");
                } while (v < target);
            }
            __syncthreads();
            for (int r = w; r < OUT_N; r += 16) {
                const float* wr = &W2[(size_t)r * MLP_HID_N];
                float acc = 0.f;
                for (int c = lane; c < MLP_HID_N; c += 32)
                    acc += wr[c] * __ldcg(&g_hid[c]);
                acc += __shfl_xor_sync(0xffffffffu, acc, 16);
                acc += __shfl_xor_sync(0xffffffffu, acc, 8);
                acc += __shfl_xor_sync(0xffffffffu, acc, 4);
                acc += __shfl_xor_sync(0xffffffffu, acc, 2);
                acc += __shfl_xor_sync(0xffffffffu, acc, 1);
                if (lane == 0) out[r] = acc + b2[r];
            }
        }
    }
}

// ---------------- launch ----------------
extern "C" void kernel_launch(void* const* d_in, const int* in_sizes, int n_in,
                              void* d_out, int out_size) {
    const float* inp  = (const float*)d_in[0];
    const float* W_ih = (const float*)d_in[1];
    const float* W_hh = (const float*)d_in[2];
    const float* b_ih = (const float*)d_in[3];
    const float* b_hh = (const float*)d_in[4];
    const float* W1   = (const float*)d_in[5];
    const float* b1   = (const float*)d_in[6];
    const float* W2   = (const float*)d_in[7];
    const float* b2   = (const float*)d_in[8];
    float* out = (float*)d_out;

    size_t smem_bytes = (size_t)(NB * WPAD_B + 1504 + NROWS * 17 + NROWS + 16)
                        * sizeof(float);
    cudaFuncSetAttribute(lstm_kernel, cudaFuncAttributeMaxDynamicSharedMemorySize,
                         (int)smem_bytes);

    pre_kernel<<<dim3(24, 32), 256>>>(inp, W_ih, b_ih, b_hh);
    lstm_kernel<<<NCTA, NTHREADS, smem_bytes>>>(W_hh, W1, b1, W2, b2, out);
}

// round 8
// speedup vs baseline: 1.4113x; 1.0456x over previous
#include <cuda_runtime.h>
#include <cstdint>

#define H_N      1500
#define G4       6000
#define T_STEPS  4096
#define MLP_HID_N 1875
#define OUT_N    20
#define IN_N     20
#define NCTA     125         // 125 CTAs x 12 units = 1500: perfectly balanced
#define NTHREADS 512
#define NU       12          // hidden units per CTA
#define NROWS    48          // gate rows per CTA
#define NB       16          // plane-B rows (smem)
#define NREP     4           // h replication factor
#define WPAD_B   1508        // B row stride (floats)
#define NCHUNK   24          // max float4 column-chunks per warp (375 = 7*24 + 9*23)

// ---------------- device scratch ----------------
__device__ float    g_xp[(size_t)T_STEPS * G4];
__device__ float    g_hrep[2][NREP][1504];     // double-buffered, replicated h
__device__ float    g_hid[MLP_HID_N];
__device__ unsigned g_count;                   // arrival counter (monotonic per launch)

#define FMA2(acc, a, b) \
    asm("fma.rn.f32x2 %0, %1, %2, %0;" : "+l"(acc) : "l"(a), "l"(b))

__device__ __forceinline__ float sigmoid_f(float x) {
    return __fdividef(1.f, 1.f + __expf(-x));
}
__device__ __forceinline__ float tanh_f(float x) {
    return __fdividef(2.f, 1.f + __expf(-2.f * x)) - 1.f;
}

__device__ __forceinline__ void cp_async16(uint32_t dst, const float* src) {
    asm volatile("cp.async.cg.shared.global [%0], [%1], 16;" :: "r"(dst), "l"(src));
}
#define CP_COMMIT() asm volatile("cp.async.commit_group;" ::: "memory")
#define CP_WAIT3()  asm volatile("cp.async.wait_group 3;" ::: "memory")

// ---------------- grid barrier (R3-proven form) ----------------
__device__ __forceinline__ void gb_arrive_wait(unsigned target) {
    asm volatile("red.release.gpu.global.add.u32 [%0], 1;"
                 :: "l"(&g_count) : "memory");
    unsigned v;
    do {
        asm volatile("ld.acquire.gpu.global.u32 %0, [%1];"
                     : "=r"(v) : "l"(&g_count) : "memory");
    } while (v < target);
}

// ---------------- pre: init state + x_proj ----------------
__global__ void pre_kernel(const float* __restrict__ inp,
                           const float* __restrict__ W_ih,
                           const float* __restrict__ b_ih,
                           const float* __restrict__ b_hh) {
    __shared__ float Wsm[256 * 21];
    __shared__ float bsm[256];
    __shared__ float insm[128 * IN_N];
    int tid = threadIdx.x;
    int r0 = blockIdx.x * 256;
    int t0 = blockIdx.y * 128;

    if (blockIdx.x == 0 && blockIdx.y == 0) {
        float* hz = &g_hrep[0][0][0];
        for (int i = tid; i < 2 * NREP * 1504; i += 256) hz[i] = 0.f;
        if (tid == 0) g_count = 0u;
    }

    for (int i = tid; i < 256 * IN_N; i += 256) {
        int rr = i / IN_N, k = i % IN_N;
        int row = r0 + rr;
        Wsm[rr * 21 + k] = (row < G4) ? W_ih[row * IN_N + k] : 0.f;
    }
    {
        int row = r0 + tid;
        bsm[tid] = (row < G4) ? (b_ih[row] + b_hh[row]) : 0.f;
    }
    for (int i = tid; i < 128 * IN_N; i += 256)
        insm[i] = inp[t0 * IN_N + i];
    __syncthreads();

    int row = r0 + tid;
    if (row < G4) {
        const float* wrow = &Wsm[tid * 21];
        float bias = bsm[tid];
        for (int tt = 0; tt < 128; tt++) {
            const float* ir = &insm[tt * IN_N];
            float acc = bias;
            #pragma unroll
            for (int k = 0; k < IN_N; k++) acc += ir[k] * wrow[k];
            g_xp[(size_t)(t0 + tt) * G4 + row] = acc;
        }
    }
}

// ---------------- persistent LSTM + MLP ----------------
__global__ void __launch_bounds__(NTHREADS, 1)
lstm_kernel(const float* __restrict__ W_hh,
            const float* __restrict__ W1,
            const float* __restrict__ b1,
            const float* __restrict__ W2,
            const float* __restrict__ b2,
            float* __restrict__ out) {
    extern __shared__ float smem[];
    float* Wb_s  = smem;                         // NB * WPAD_B = 24128
    float* h_s   = Wb_s + NB * WPAD_B;           // 1504
    float* part  = h_s + 1504;                   // NROWS * 17 = 816
    float* xpr   = part + NROWS * 17;            // ring: 4 * 48 = 192
    float* c_s   = xpr + 4 * NROWS;              // 16

    const int tid  = threadIdx.x;
    const int lane = tid & 31;
    const int w    = tid >> 5;
    const int b    = blockIdx.x;
    const int u0   = b * NU;

    const int NK    = (w < 7) ? 24 : 23;
    const int start = (w < 7) ? w * 24 : 168 + (w - 7) * 23;

    // ---- preload plane-B weights (rows 32..47) into smem ----
    for (int idx = tid; idx < NB * 377; idx += NTHREADS) {
        int r = idx / 377, c4 = idx % 377;
        float4 v = make_float4(0.f, 0.f, 0.f, 0.f);
        if (c4 < 375) {
            int lr = 32 + r;
            int grow = (lr / NU) * H_N + u0 + (lr % NU);
            v = *(const float4*)&W_hh[(size_t)grow * H_N + c4 * 4];
        }
        *(float4*)&Wb_s[r * WPAD_B + c4 * 4] = v;
    }
    if (tid < NU) c_s[tid] = 0.f;

    // ---- preload plane-A weights (row = lane, 32 rows) into registers ----
    ulonglong2 wA[NCHUNK];
    {
        int grow = (lane / NU) * H_N + u0 + (lane % NU);
        const float* wrowA = &W_hh[(size_t)grow * H_N];
        #pragma unroll
        for (int k = 0; k < NCHUNK; k++) {
            if (k < NK)
                wA[k] = *(const ulonglong2*)&wrowA[(start + k) * 4];
            else
                wA[k] = make_ulonglong2(0ull, 0ull);
        }
    }

    // plane-B: lanes mirror rows (lane % 16)
    const float* wrowB = &Wb_s[(lane & (NB - 1)) * WPAD_B];

    // ---- prime cp.async xp ring (steps 0..3), one 16B piece per thread<12 ----
    const uint32_t xr_base = (uint32_t)__cvta_generic_to_shared(xpr);
    const int gate = tid / 3, jj = tid % 3;      // valid for tid<12
    if (tid < 12) {
        #pragma unroll
        for (int tt = 0; tt < 4; tt++) {
            cp_async16(xr_base + (uint32_t)((tt * NROWS + gate * NU + jj * 4) * 4),
                       &g_xp[(size_t)tt * G4 + gate * H_N + u0 + jj * 4]);
            CP_COMMIT();
        }
    }

    __syncthreads();

    for (int t = 0; t < T_STEPS; t++) {
        // complete xp group for step t (issuers only), then publish via syncthreads
        if (tid < 12) CP_WAIT3();

        // h(t) load and stage to smem
        const float* hb = g_hrep[t & 1][b & (NREP - 1)];
        if (tid < 376) {
            float4 hv4 = __ldcg((const float4*)&hb[tid * 4]);
            *(float4*)&h_s[tid * 4] = hv4;
        }
        __syncthreads();

        // ---- matvec: packed f32x2 FMAs; A from regs, B via LDS.128 ----
        unsigned long long aA0 = 0ull, aA1 = 0ull, aB0 = 0ull, aB1 = 0ull;
        const float* hbase = &h_s[start * 4];
        #pragma unroll
        for (int k = 0; k < NCHUNK; k++) {
            ulonglong2 hv = (k < NK) ? *(const ulonglong2*)&hbase[k * 4]
                                     : make_ulonglong2(0ull, 0ull);
            FMA2(aA0, wA[k].x, hv.x);
            FMA2(aA1, wA[k].y, hv.y);
            ulonglong2 wb = (k < NK) ? *(const ulonglong2*)&wrowB[(start + k) * 4]
                                     : make_ulonglong2(0ull, 0ull);
            FMA2(aB0, wb.x, hv.x);
            FMA2(aB1, wb.y, hv.y);
        }
        float accA, accB;
        {
            float2 a0 = *(float2*)&aA0, a1 = *(float2*)&aA1;
            accA = (a0.x + a0.y) + (a1.x + a1.y);
            float2 b0 = *(float2*)&aB0, b1 = *(float2*)&aB1;
            accB = (b0.x + b0.y) + (b1.x + b1.y);
        }
        part[lane * 17 + w] = accA;                       // 32 A rows
        if (lane < NB) part[(32 + lane) * 17 + w] = accB; // 16 B rows
        __syncthreads();

        // ---- reduce + gates: warp u owns unit u; half-warp paired rows ----
        if (w < NU) {
            const float* xps = &xpr[(t & 3) * NROWS];
            const int half = lane >> 4;          // 0: rows {u, 24+u}, 1: {12+u, 36+u}
            const int l15  = lane & 15;

            // batch 1: rows u (i-gate) and 12+u (f-gate) — both sigmoid
            int r01 = w + half * 12;
            float v01 = part[r01 * 17 + l15];
            v01 += __shfl_xor_sync(0xffffffffu, v01, 8);
            v01 += __shfl_xor_sync(0xffffffffu, v01, 4);
            v01 += __shfl_xor_sync(0xffffffffu, v01, 2);
            v01 += __shfl_xor_sync(0xffffffffu, v01, 1);
            v01 += xps[r01];
            float act01 = sigmoid_f(v01);

            // batch 2: rows 24+u (g: tanh) and 36+u (o: sigmoid), branch-free
            int r23 = 24 + w + half * 12;
            float v23 = part[r23 * 17 + l15];
            v23 += __shfl_xor_sync(0xffffffffu, v23, 8);
            v23 += __shfl_xor_sync(0xffffffffu, v23, 4);
            v23 += __shfl_xor_sync(0xffffffffu, v23, 2);
            v23 += __shfl_xor_sync(0xffffffffu, v23, 1);
            v23 += xps[r23];
            float s = half ? 1.f : 2.f;          // tanh(x)=2*sig(2x)-1
            float act23 = s * __fdividef(1.f, 1.f + __expf(-s * v23)) - (s - 1.f);

            float ig = __shfl_sync(0xffffffffu, act01, 0);
            float fg = __shfl_sync(0xffffffffu, act01, 16);
            float gg = __shfl_sync(0xffffffffu, act23, 0);
            float og = __shfl_sync(0xffffffffu, act23, 16);

            float c = fg * c_s[w] + ig * gg;     // all lanes redundantly
            float hval = og * tanh_f(c);
            if (lane == 0) c_s[w] = c;
            if (lane < NREP)
                g_hrep[(t + 1) & 1][lane][u0 + w] = hval;
        }

        // producer warps (0-11) sync among themselves; then issue xp(t+4) + arrive
        if (tid < 384)
            asm volatile("bar.sync 1, 384;" ::: "memory");
        if (tid < 12) {
            if (t + 4 < T_STEPS)
                cp_async16(xr_base + (uint32_t)((((t + 4) & 3) * NROWS + gate * NU + jj * 4) * 4),
                           &g_xp[(size_t)(t + 4) * G4 + gate * H_N + u0 + jj * 4]);
            CP_COMMIT();
        }
        if (tid == 0) gb_arrive_wait((unsigned)NCTA * (unsigned)(t + 1));
        __syncthreads();
    }

    // =================== MLP head (h final in g_hrep[0][*]) ===================
    {
        int gw = b * 16 + w;
        if (gw < MLP_HID_N) {
            const float* wr = &W1[(size_t)gw * H_N];
            const float* hv = g_hrep[0][b & (NREP - 1)];
            float acc = 0.f;
            for (int c4 = lane; c4 < 375; c4 += 32) {
                float4 wv = *(const float4*)&wr[c4 * 4];
                float4 h4 = __ldcg((const float4*)&hv[c4 * 4]);
                acc += wv.x * h4.x + wv.y * h4.y + wv.z * h4.z + wv.w * h4.w;
            }
            acc += __shfl_xor_sync(0xffffffffu, acc, 16);
            acc += __shfl_xor_sync(0xffffffffu, acc, 8);
            acc += __shfl_xor_sync(0xffffffffu, acc, 4);
            acc += __shfl_xor_sync(0xffffffffu, acc, 2);
            acc += __shfl_xor_sync(0xffffffffu, acc, 1);
            if (lane == 0) g_hid[gw] = acc + b1[gw];
        }
        __syncthreads();
        if (tid == 0) {
            asm volatile("red.release.gpu.global.add.u32 [%0], 1;"
                         :: "l"(&g_count) : "memory");
        }

        if (b == 0) {
            if (tid == 0) {
                unsigned v, target = (unsigned)NCTA * (unsigned)(T_STEPS + 1);
                do {
                    asm volatile("ld.acquire.gpu.global.u32 %0, [%1];"
                                 : "=r"(v) : "l"(&g_count) : "memory");
                } while (v < target);
            }
            __syncthreads();
            for (int r = w; r < OUT_N; r += 16) {
                const float* wr = &W2[(size_t)r * MLP_HID_N];
                float acc = 0.f;
                for (int c = lane; c < MLP_HID_N; c += 32)
                    acc += wr[c] * __ldcg(&g_hid[c]);
                acc += __shfl_xor_sync(0xffffffffu, acc, 16);
                acc += __shfl_xor_sync(0xffffffffu, acc, 8);
                acc += __shfl_xor_sync(0xffffffffu, acc, 4);
                acc += __shfl_xor_sync(0xffffffffu, acc, 2);
                acc += __shfl_xor_sync(0xffffffffu, acc, 1);
                if (lane == 0) out[r] = acc + b2[r];
            }
        }
    }
}

// ---------------- launch ----------------
extern "C" void kernel_launch(void* const* d_in, const int* in_sizes, int n_in,
                              void* d_out, int out_size) {
    const float* inp  = (const float*)d_in[0];
    const float* W_ih = (const float*)d_in[1];
    const float* W_hh = (const float*)d_in[2];
    const float* b_ih = (const float*)d_in[3];
    const float* b_hh = (const float*)d_in[4];
    const float* W1   = (const float*)d_in[5];
    const float* b1   = (const float*)d_in[6];
    const float* W2   = (const float*)d_in[7];
    const float* b2   = (const float*)d_in[8];
    float* out = (float*)d_out;

    size_t smem_bytes = (size_t)(NB * WPAD_B + 1504 + NROWS * 17 + 4 * NROWS + 16)
                        * sizeof(float);
    cudaFuncSetAttribute(lstm_kernel, cudaFuncAttributeMaxDynamicSharedMemorySize,
                         (int)smem_bytes);

    pre_kernel<<<dim3(24, 32), 256>>>(inp, W_ih, b_ih, b_hh);
    lstm_kernel<<<NCTA, NTHREADS, smem_bytes>>>(W_hh, W1, b1, W2, b2, out);
}

// round 9
// speedup vs baseline: 1.5639x; 1.1081x over previous
#include <cuda_runtime.h>
#include <cstdint>

#define H_N      1500
#define G4       6000
#define T_STEPS  4096
#define MLP_HID_N 1875
#define OUT_N    20
#define IN_N     20
#define NCTA     125         // 125 CTAs x 12 units = 1500
#define NLO      63          // CTAs 0..62 produce h[0:756)  (float4 0..188)
#define NHI      62          // CTAs 63..124 produce h[756:1500)
#define NTHREADS 512
#define NU       12
#define NROWS    48
#define NB       16          // plane-B rows (smem)
#define NREP     4           // h replication factor
#define WPAD_B   1508
#define NCHUNK   24          // 375 = 7*24 + 9*23

// ---------------- device scratch ----------------
__device__ float    g_xp[(size_t)T_STEPS * G4];
__device__ float    g_hrep[2][NREP][1504];
__device__ float    g_hid[MLP_HID_N];
__device__ unsigned g_cnt[384];   // [0]=lo, [256]=hi, [128]=mlp (separate lines)

#define FMA2(acc, a, b) \
    asm("fma.rn.f32x2 %0, %1, %2, %0;" : "+l"(acc) : "l"(a), "l"(b))

__device__ __forceinline__ float sigmoid_f(float x) {
    return __fdividef(1.f, 1.f + __expf(-x));
}
__device__ __forceinline__ float tanh_f(float x) {
    return __fdividef(2.f, 1.f + __expf(-2.f * x)) - 1.f;
}

__device__ __forceinline__ void cp_async16(uint32_t dst, const float* src) {
    asm volatile("cp.async.cg.shared.global [%0], [%1], 16;" :: "r"(dst), "l"(src));
}
#define CP_COMMIT() asm volatile("cp.async.commit_group;" ::: "memory")
#define CP_WAIT3()  asm volatile("cp.async.wait_group 3;" ::: "memory")

__device__ __forceinline__ unsigned ld_acq_g(const unsigned* p) {
    unsigned v;
    asm volatile("ld.acquire.gpu.global.u32 %0, [%1];" : "=r"(v) : "l"(p) : "memory");
    return v;
}
__device__ __forceinline__ void red_rel_g(unsigned* p) {
    asm volatile("red.release.gpu.global.add.u32 [%0], 1;" :: "l"(p) : "memory");
}
__device__ __forceinline__ void st_rel_s(uint32_t a, unsigned v) {
    asm volatile("st.release.cta.shared.u32 [%0], %1;" :: "r"(a), "r"(v) : "memory");
}
__device__ __forceinline__ unsigned ld_acq_s(uint32_t a) {
    unsigned v;
    asm volatile("ld.acquire.cta.shared.u32 %0, [%1];" : "=r"(v) : "r"(a) : "memory");
    return v;
}

// ---------------- pre: init state + x_proj ----------------
__global__ void pre_kernel(const float* __restrict__ inp,
                           const float* __restrict__ W_ih,
                           const float* __restrict__ b_ih,
                           const float* __restrict__ b_hh) {
    __shared__ float Wsm[256 * 21];
    __shared__ float bsm[256];
    __shared__ float insm[128 * IN_N];
    int tid = threadIdx.x;
    int r0 = blockIdx.x * 256;
    int t0 = blockIdx.y * 128;

    if (blockIdx.x == 0 && blockIdx.y == 0) {
        float* hz = &g_hrep[0][0][0];
        for (int i = tid; i < 2 * NREP * 1504; i += 256) hz[i] = 0.f;
        for (int i = tid; i < 384; i += 256) g_cnt[i] = 0u;
    }

    for (int i = tid; i < 256 * IN_N; i += 256) {
        int rr = i / IN_N, k = i % IN_N;
        int row = r0 + rr;
        Wsm[rr * 21 + k] = (row < G4) ? W_ih[row * IN_N + k] : 0.f;
    }
    {
        int row = r0 + tid;
        bsm[tid] = (row < G4) ? (b_ih[row] + b_hh[row]) : 0.f;
    }
    for (int i = tid; i < 128 * IN_N; i += 256)
        insm[i] = inp[t0 * IN_N + i];
    __syncthreads();

    int row = r0 + tid;
    if (row < G4) {
        const float* wrow = &Wsm[tid * 21];
        float bias = bsm[tid];
        for (int tt = 0; tt < 128; tt++) {
            const float* ir = &insm[tt * IN_N];
            float acc = bias;
            #pragma unroll
            for (int k = 0; k < IN_N; k++) acc += ir[k] * wrow[k];
            g_xp[(size_t)(t0 + tt) * G4 + row] = acc;
        }
    }
}

// ---------------- persistent LSTM + MLP ----------------
__global__ void __launch_bounds__(NTHREADS, 1)
lstm_kernel(const float* __restrict__ W_hh,
            const float* __restrict__ W1,
            const float* __restrict__ b1,
            const float* __restrict__ W2,
            const float* __restrict__ b2,
            float* __restrict__ out) {
    extern __shared__ float smem[];
    float* Wb_s  = smem;                         // NB * WPAD_B
    float* h_s   = Wb_s + NB * WPAD_B;           // 1504
    float* part  = h_s + 1504;                   // NROWS * 17
    float* xpr   = part + NROWS * 17;            // 4 * 48
    float* c_s   = xpr + 4 * NROWS;              // 16
    unsigned* uflag = (unsigned*)(c_s + 16);     // 2 step flags (lo, hi)

    const int tid  = threadIdx.x;
    const int lane = tid & 31;
    const int w    = tid >> 5;
    const int b    = blockIdx.x;
    const int u0   = b * NU;

    const int NK    = (w < 7) ? 24 : 23;
    const int start = (w < 7) ? w * 24 : 168 + (w - 7) * 23;

    const uint32_t fl_lo = (uint32_t)__cvta_generic_to_shared(uflag);
    const uint32_t fl_hi = fl_lo + 4;

    // ---- preload plane-B weights (rows 32..47) into smem ----
    for (int idx = tid; idx < NB * 377; idx += NTHREADS) {
        int r = idx / 377, c4 = idx % 377;
        float4 v = make_float4(0.f, 0.f, 0.f, 0.f);
        if (c4 < 375) {
            int lr = 32 + r;
            int grow = (lr / NU) * H_N + u0 + (lr % NU);
            v = *(const float4*)&W_hh[(size_t)grow * H_N + c4 * 4];
        }
        *(float4*)&Wb_s[r * WPAD_B + c4 * 4] = v;
    }
    if (tid < NU) c_s[tid] = 0.f;
    if (tid < 2) uflag[tid] = 0u;

    // ---- preload plane-A weights (row = lane, 32 rows) into registers ----
    ulonglong2 wA[NCHUNK];
    {
        int grow = (lane / NU) * H_N + u0 + (lane % NU);
        const float* wrowA = &W_hh[(size_t)grow * H_N];
        #pragma unroll
        for (int k = 0; k < NCHUNK; k++) {
            if (k < NK)
                wA[k] = *(const ulonglong2*)&wrowA[(start + k) * 4];
            else
                wA[k] = make_ulonglong2(0ull, 0ull);
        }
    }

    // plane-B column-split: lanes 0-15 take chunks [start,start+12),
    // lanes 16-31 take [start+12, start+NK); row = lane&15
    const int half   = lane >> 4;
    const int bcnt   = half ? (NK - 12) : 12;
    const float* wbB = &Wb_s[(lane & 15) * WPAD_B + (start + half * 12) * 4];

    // ---- prime cp.async xp ring (steps 0..3) ----
    const uint32_t xr_base = (uint32_t)__cvta_generic_to_shared(xpr);
    const int gate = tid / 3, jj = tid % 3;      // valid for tid<12
    if (tid < 12) {
        #pragma unroll
        for (int tt = 0; tt < 4; tt++) {
            cp_async16(xr_base + (uint32_t)((tt * NROWS + gate * NU + jj * 4) * 4),
                       &g_xp[(size_t)tt * G4 + gate * H_N + u0 + jj * 4]);
            CP_COMMIT();
        }
    }

    __syncthreads();

    for (int t = 0; t < T_STEPS; t++) {
        // ---- per-warp h readiness (split counters) + private staging ----
        if (w == 0) {
            unsigned tgt = (unsigned)NLO * (unsigned)t;
            while (ld_acq_g(&g_cnt[0]) < tgt) {}
            if (lane == 0) st_rel_s(fl_lo, (unsigned)t + 1u);
        } else if (w == 8) {
            unsigned tgt = (unsigned)NHI * (unsigned)t;
            while (ld_acq_g(&g_cnt[256]) < tgt) {}
            if (lane == 0) st_rel_s(fl_hi, (unsigned)t + 1u);
        } else if (w <= 6) {
            while (ld_acq_s(fl_lo) < (unsigned)t + 1u) {}
        } else if (w == 7) {
            while (ld_acq_s(fl_lo) < (unsigned)t + 1u) {}
            while (ld_acq_s(fl_hi) < (unsigned)t + 1u) {}
        } else {
            while (ld_acq_s(fl_hi) < (unsigned)t + 1u) {}
        }
        // stage this warp's own h chunk range
        {
            const float4* hb4 = (const float4*)g_hrep[t & 1][b & (NREP - 1)];
            if (lane < NK) {
                float4 v = __ldcg(&hb4[start + lane]);
                *(float4*)&h_s[(start + lane) * 4] = v;
            }
            __syncwarp();
        }

        // ---- matvec: A-plane (32 rows, uniform hv) + split B-plane ----
        unsigned long long aA0 = 0ull, aA1 = 0ull, aB0 = 0ull, aB1 = 0ull;
        const float* hbase = &h_s[start * 4];
        #pragma unroll
        for (int k = 0; k < NCHUNK; k++) {
            ulonglong2 hv = (k < NK) ? *(const ulonglong2*)&hbase[k * 4]
                                     : make_ulonglong2(0ull, 0ull);
            FMA2(aA0, wA[k].x, hv.x);
            FMA2(aA1, wA[k].y, hv.y);
        }
        const float* hbB = &h_s[(start + half * 12) * 4];
        #pragma unroll
        for (int k = 0; k < 12; k++) {
            bool ok = (k < bcnt);
            ulonglong2 hv = ok ? *(const ulonglong2*)&hbB[k * 4]
                               : make_ulonglong2(0ull, 0ull);
            ulonglong2 wb = ok ? *(const ulonglong2*)&wbB[k * 4]
                               : make_ulonglong2(0ull, 0ull);
            FMA2(aB0, wb.x, hv.x);
            FMA2(aB1, wb.y, hv.y);
        }
        float accA, accB;
        {
            float2 a0 = *(float2*)&aA0, a1 = *(float2*)&aA1;
            accA = (a0.x + a0.y) + (a1.x + a1.y);
            float2 b0 = *(float2*)&aB0, b1 = *(float2*)&aB1;
            accB = (b0.x + b0.y) + (b1.x + b1.y);
        }
        accB += __shfl_xor_sync(0xffffffffu, accB, 16);   // combine column halves
        part[lane * 17 + w] = accA;
        if (lane < NB) part[(32 + lane) * 17 + w] = accB;
        if (w == 0) CP_WAIT3();
        __syncthreads();

        // ---- paired reduce + gates: warp u owns unit u (R8 scheme) ----
        if (w < NU) {
            const float* xps = &xpr[(t & 3) * NROWS];
            const int rhalf = lane >> 4;
            const int l15   = lane & 15;

            int r01 = w + rhalf * 12;            // i (u) / f (12+u)
            float v01 = part[r01 * 17 + l15];
            v01 += __shfl_xor_sync(0xffffffffu, v01, 8);
            v01 += __shfl_xor_sync(0xffffffffu, v01, 4);
            v01 += __shfl_xor_sync(0xffffffffu, v01, 2);
            v01 += __shfl_xor_sync(0xffffffffu, v01, 1);
            v01 += xps[r01];
            float act01 = sigmoid_f(v01);

            int r23 = 24 + w + rhalf * 12;       // g (24+u) / o (36+u)
            float v23 = part[r23 * 17 + l15];
            v23 += __shfl_xor_sync(0xffffffffu, v23, 8);
            v23 += __shfl_xor_sync(0xffffffffu, v23, 4);
            v23 += __shfl_xor_sync(0xffffffffu, v23, 2);
            v23 += __shfl_xor_sync(0xffffffffu, v23, 1);
            v23 += xps[r23];
            float s = rhalf ? 1.f : 2.f;         // tanh(x)=2*sig(2x)-1
            float act23 = s * __fdividef(1.f, 1.f + __expf(-s * v23)) - (s - 1.f);

            float ig = __shfl_sync(0xffffffffu, act01, 0);
            float fg = __shfl_sync(0xffffffffu, act01, 16);
            float gg = __shfl_sync(0xffffffffu, act23, 0);
            float og = __shfl_sync(0xffffffffu, act23, 16);

            float c = fg * c_s[w] + ig * gg;
            float hval = og * tanh_f(c);
            if (lane == 0) c_s[w] = c;
            if (lane < NREP)
                g_hrep[(t + 1) & 1][lane][u0 + w] = hval;
        }

        // producers sync; xp(t+4) prefetch; arrive at my group counter
        if (tid < 384)
            asm volatile("bar.sync 1, 384;" ::: "memory");
        if (tid < 12) {
            if (t + 4 < T_STEPS)
                cp_async16(xr_base + (uint32_t)((((t + 4) & 3) * NROWS + gate * NU + jj * 4) * 4),
                           &g_xp[(size_t)(t + 4) * G4 + gate * H_N + u0 + jj * 4]);
            CP_COMMIT();
        }
        if (tid == 0) red_rel_g((b < NLO) ? &g_cnt[0] : &g_cnt[256]);
        __syncthreads();   // protects part[] (WAR) and h_s staging order
    }

    // wait for ALL CTAs' final h before the MLP reads it
    if (tid == 0) {
        while (ld_acq_g(&g_cnt[0])   < (unsigned)NLO * (unsigned)T_STEPS) {}
        while (ld_acq_g(&g_cnt[256]) < (unsigned)NHI * (unsigned)T_STEPS) {}
    }
    __syncthreads();

    // =================== MLP head (h final in g_hrep[0][*]) ===================
    {
        int gw = b * 16 + w;
        if (gw < MLP_HID_N) {
            const float* wr = &W1[(size_t)gw * H_N];
            const float* hv = g_hrep[0][b & (NREP - 1)];
            float acc = 0.f;
            for (int c4 = lane; c4 < 375; c4 += 32) {
                float4 wv = *(const float4*)&wr[c4 * 4];
                float4 h4 = __ldcg((const float4*)&hv[c4 * 4]);
                acc += wv.x * h4.x + wv.y * h4.y + wv.z * h4.z + wv.w * h4.w;
            }
            acc += __shfl_xor_sync(0xffffffffu, acc, 16);
            acc += __shfl_xor_sync(0xffffffffu, acc, 8);
            acc += __shfl_xor_sync(0xffffffffu, acc, 4);
            acc += __shfl_xor_sync(0xffffffffu, acc, 2);
            acc += __shfl_xor_sync(0xffffffffu, acc, 1);
            if (lane == 0) g_hid[gw] = acc + b1[gw];
        }
        __syncthreads();
        if (tid == 0) red_rel_g(&g_cnt[128]);

        if (b == 0) {
            if (tid == 0) {
                while (ld_acq_g(&g_cnt[128]) < (unsigned)NCTA) {}
            }
            __syncthreads();
            for (int r = w; r < OUT_N; r += 16) {
                const float* wr = &W2[(size_t)r * MLP_HID_N];
                float acc = 0.f;
                for (int c = lane; c < MLP_HID_N; c += 32)
                    acc += wr[c] * __ldcg(&g_hid[c]);
                acc += __shfl_xor_sync(0xffffffffu, acc, 16);
                acc += __shfl_xor_sync(0xffffffffu, acc, 8);
                acc += __shfl_xor_sync(0xffffffffu, acc, 4);
                acc += __shfl_xor_sync(0xffffffffu, acc, 2);
                acc += __shfl_xor_sync(0xffffffffu, acc, 1);
                if (lane == 0) out[r] = acc + b2[r];
            }
        }
    }
}

// ---------------- launch ----------------
extern "C" void kernel_launch(void* const* d_in, const int* in_sizes, int n_in,
                              void* d_out, int out_size) {
    const float* inp  = (const float*)d_in[0];
    const float* W_ih = (const float*)d_in[1];
    const float* W_hh = (const float*)d_in[2];
    const float* b_ih = (const float*)d_in[3];
    const float* b_hh = (const float*)d_in[4];
    const float* W1   = (const float*)d_in[5];
    const float* b1   = (const float*)d_in[6];
    const float* W2   = (const float*)d_in[7];
    const float* b2   = (const float*)d_in[8];
    float* out = (float*)d_out;

    size_t smem_bytes = (size_t)(NB * WPAD_B + 1504 + NROWS * 17 + 4 * NROWS + 16 + 8)
                        * sizeof(float);
    cudaFuncSetAttribute(lstm_kernel, cudaFuncAttributeMaxDynamicSharedMemorySize,
                         (int)smem_bytes);

    pre_kernel<<<dim3(24, 32), 256>>>(inp, W_ih, b_ih, b_hh);
    lstm_kernel<<<NCTA, NTHREADS, smem_bytes>>>(W_hh, W1, b1, W2, b2, out);
}